// round 6
// baseline (speedup 1.0000x reference)
#include <cuda_runtime.h>
#include <cstdint>

#define NB 32
#define NS 1024
#define NI 256
#define NH 512
#define NO 256

// Scratch: device globals (no allocations allowed)
__device__ float    g_inp_cur[(size_t)NB * NS * NH];     // 64 MB
__device__ unsigned g_spike_bits[(size_t)NB * NS * 16];  // 2 MB packed spikes

// ---------------------------------------------------------------------------
// K1: inp_cur[b*s, h] = X[b*s, i] @ Wi[i, h]   (fp32 SIMT tiled GEMM, at FMA peak)
// ---------------------------------------------------------------------------
__global__ __launch_bounds__(256) void k1_gemm(const float* __restrict__ X,
                                               const float* __restrict__ Wi) {
    __shared__ float As[64][33];
    __shared__ float Bs[32][64];
    const int m0 = blockIdx.y * 64, n0 = blockIdx.x * 64;
    const int tid = threadIdx.x;
    const int tm = tid >> 4, tn = tid & 15;

    float acc[4][4];
#pragma unroll
    for (int i = 0; i < 4; i++)
#pragma unroll
        for (int j = 0; j < 4; j++) acc[i][j] = 0.f;

    for (int k0 = 0; k0 < NI; k0 += 32) {
#pragma unroll
        for (int e = 0; e < 8; e++) {
            int idx = tid + e * 256;
            As[idx >> 5][idx & 31] = X[(size_t)(m0 + (idx >> 5)) * NI + k0 + (idx & 31)];
        }
#pragma unroll
        for (int e = 0; e < 8; e++) {
            int idx = tid + e * 256;
            Bs[idx >> 6][idx & 63] = Wi[(size_t)(k0 + (idx >> 6)) * NH + n0 + (idx & 63)];
        }
        __syncthreads();
#pragma unroll
        for (int k = 0; k < 32; k++) {
            float a[4];
#pragma unroll
            for (int i = 0; i < 4; i++) a[i] = As[tm * 4 + i][k];
            float4 bv = *reinterpret_cast<const float4*>(&Bs[k][tn * 4]);
            float b[4] = {bv.x, bv.y, bv.z, bv.w};
#pragma unroll
            for (int i = 0; i < 4; i++)
#pragma unroll
                for (int j = 0; j < 4; j++) acc[i][j] += a[i] * b[j];
        }
        __syncthreads();
    }
#pragma unroll
    for (int i = 0; i < 4; i++) {
        float4 v = make_float4(acc[i][0], acc[i][1], acc[i][2], acc[i][3]);
        *reinterpret_cast<float4*>(
            &g_inp_cur[(size_t)(m0 + tm * 4 + i) * NH + n0 + tn * 4]) = v;
    }
}

// ---------------------------------------------------------------------------
// Warp-cooperative bit compaction (16 words = 512 bits -> ascending u16 list).
// Used by K3 only.
// ---------------------------------------------------------------------------
__device__ __forceinline__ int compact_warp(const unsigned* words, unsigned short* list) {
    const int lane = threadIdx.x & 31;
    unsigned w = words[lane >> 1];
    unsigned m = (lane & 1) ? (w >> 16) : (w & 0xFFFFu);
    int cnt = __popc(m);
    int sc = cnt;
#pragma unroll
    for (int d = 1; d < 32; d <<= 1) {
        int v = __shfl_up_sync(0xffffffffu, sc, d);
        if (lane >= d) sc += v;
    }
    int total = __shfl_sync(0xffffffffu, sc, 31);
    int off = sc - cnt;
    int base = (lane >> 1) * 32 + (lane & 1) * 16;
    while (m) {
        int j = __ffs(m) - 1;
        m &= m - 1;
        list[off++] = (unsigned short)(base + j);
    }
    return total;
}

// ---------------------------------------------------------------------------
// K2: one CTA per batch (32 CTAs x 512 threads), recurrence fully CTA-local.
// Thread j owns neuron j. Spike list is kept as 16 fixed 32-entry segments
// (one per warp); compaction is INLINE at update time:
//   off = popc(ballot & lanemask_lt); if (spike) s_list[warp*32+off] = tid
// Per step:  gather (prev lists) -> bar -> update + ballot + inline compact
//            -> bar.   (2 barriers, no dedicated compact phase)
// Gather: 4 teams of 128 threads; team k walks segments 4k..4k+3; each thread
// covers cols 4c..4c+3 via coalesced LDG.128 of W_lat rows (L2-resident).
// ---------------------------------------------------------------------------
__global__ __launch_bounds__(512, 1) void k2_scan(const float* __restrict__ Wl,
                                                  const float* __restrict__ thr) {
    __shared__ __align__(16) unsigned short s_list[16 * 32];  // 16 segments x 32
    __shared__ int s_cnt[16];                                 // per-segment counts
    __shared__ float s_part[4 * 512];                         // team partials

    const int tid  = threadIdx.x;
    const int b    = blockIdx.x;
    const int warp = tid >> 5, lane = tid & 31;
    const int team = tid >> 7, c = tid & 127;  // team 0..3, cols 4c..4c+3

    if (tid < 16) s_cnt[tid] = 0;  // empty lists at t=0

    float mp = 0.f;
    int refrac = 0;
    const float th = thr[tid];
    const float* icp = g_inp_cur + (size_t)b * NS * NH + tid;
    const float* Wcol = Wl + 4 * c;  // + i*NH -> row i, cols 4c..4c+3
    const size_t bits_base = (size_t)b * NS * 16;

    __syncthreads();

    for (int t = 0; t < NS; t++) {
        const float ic = icp[(size_t)t * NH];  // in flight during gather

        // --- Sparse gather over this team's 4 segments --------------------
        float4 accA = make_float4(0.f, 0.f, 0.f, 0.f);
        float4 accB = make_float4(0.f, 0.f, 0.f, 0.f);
#pragma unroll
        for (int s = 0; s < 4; s++) {
            const int seg = team * 4 + s;
            const int cnt = s_cnt[seg];  // LDS broadcast
            const uint4* Lv = (const uint4*)&s_list[seg * 32];
            for (int j = 0; j < cnt; j += 8) {
                uint4 v = Lv[j >> 3];
                unsigned id0 = v.x & 0xFFFFu, id1 = v.x >> 16;
                unsigned id2 = v.y & 0xFFFFu, id3 = v.y >> 16;
                unsigned id4 = v.z & 0xFFFFu, id5 = v.z >> 16;
                unsigned id6 = v.w & 0xFFFFu, id7 = v.w >> 16;
                const int rem = cnt - j;
                if (rem >= 8) {
                    float4 w0 = *reinterpret_cast<const float4*>(&Wcol[id0 * NH]);
                    float4 w1 = *reinterpret_cast<const float4*>(&Wcol[id1 * NH]);
                    float4 w2 = *reinterpret_cast<const float4*>(&Wcol[id2 * NH]);
                    float4 w3 = *reinterpret_cast<const float4*>(&Wcol[id3 * NH]);
                    float4 w4 = *reinterpret_cast<const float4*>(&Wcol[id4 * NH]);
                    float4 w5 = *reinterpret_cast<const float4*>(&Wcol[id5 * NH]);
                    float4 w6 = *reinterpret_cast<const float4*>(&Wcol[id6 * NH]);
                    float4 w7 = *reinterpret_cast<const float4*>(&Wcol[id7 * NH]);
                    accA.x += w0.x; accA.y += w0.y; accA.z += w0.z; accA.w += w0.w;
                    accB.x += w1.x; accB.y += w1.y; accB.z += w1.z; accB.w += w1.w;
                    accA.x += w2.x; accA.y += w2.y; accA.z += w2.z; accA.w += w2.w;
                    accB.x += w3.x; accB.y += w3.y; accB.z += w3.z; accB.w += w3.w;
                    accA.x += w4.x; accA.y += w4.y; accA.z += w4.z; accA.w += w4.w;
                    accB.x += w5.x; accB.y += w5.y; accB.z += w5.z; accB.w += w5.w;
                    accA.x += w6.x; accA.y += w6.y; accA.z += w6.z; accA.w += w6.w;
                    accB.x += w7.x; accB.y += w7.y; accB.z += w7.z; accB.w += w7.w;
                } else {
                    unsigned ids[8] = {id0, id1, id2, id3, id4, id5, id6, id7};
                    for (int k = 0; k < rem; k++) {
                        float4 w = *reinterpret_cast<const float4*>(&Wcol[ids[k] * NH]);
                        accA.x += w.x; accA.y += w.y; accA.z += w.z; accA.w += w.w;
                    }
                }
            }
        }
        accA.x += accB.x; accA.y += accB.y; accA.z += accB.z; accA.w += accB.w;
        *reinterpret_cast<float4*>(&s_part[team * 512 + 4 * c]) = accA;
        __syncthreads();  // B1: partials ready; prev lists fully consumed

        // --- Update neuron tid + inline compaction into next step's lists --
        float lat = (s_part[tid] + s_part[512 + tid]) +
                    (s_part[1024 + tid] + s_part[1536 + tid]);
        float nmp = fmaf(0.95f, mp, ic) - lat;
        if (refrac > 0) nmp = 0.f;
        refrac = (refrac > 0) ? refrac - 1 : 0;
        const bool sp = (nmp >= th);
        if (sp) { nmp = 0.f; refrac = 2; }
        mp = nmp;
        const unsigned bal = __ballot_sync(0xffffffffu, sp);
        const unsigned off = __popc(bal & ((1u << lane) - 1u));
        if (sp) s_list[warp * 32 + off] = (unsigned short)tid;
        if (lane == 0) {
            s_cnt[warp] = __popc(bal);
            g_spike_bits[bits_base + (size_t)t * 16 + warp] = bal;
        }
        __syncthreads();  // B2: lists + counts ready for next step's gather
    }
}

// ---------------------------------------------------------------------------
// K3: out[b*s, o] = spikes @ Wo, sparse from packed bits. 512 threads:
// 8 row-slots x 64 cols, 8-wide prefetched gather from smem-resident Wo slice.
// ---------------------------------------------------------------------------
#define K3_SMEM (512 * 64 * 4 + 8 * 512 * 2)
#define K3_ROWS_PER_CTA 222

__global__ __launch_bounds__(512, 1) void k3_out(const float* __restrict__ Wo,
                                                 float* __restrict__ out) {
    extern __shared__ char smem[];
    float*          Ws    = (float*)smem;                            // 512 x 64
    unsigned short* lists = (unsigned short*)(smem + 512 * 64 * 4);  // [8][512]
    __shared__ int cnts[8];

    const int tid = threadIdx.x;
    const int g = (int)blockIdx.y, chunk = (int)blockIdx.x;
    const int rs = tid >> 6, col = tid & 63;

    for (int idx = tid; idx < 512 * 64; idx += 512)
        Ws[idx] = Wo[(size_t)(idx >> 6) * NO + g * 64 + (idx & 63)];
    __syncthreads();

    const int r0 = chunk * K3_ROWS_PER_CTA;
    const int r1 = min(r0 + K3_ROWS_PER_CTA, NB * NS);
    for (int rb = r0; rb < r1; rb += 8) {
        const int r = rb + rs;
        const bool valid = (r < r1);
        if (((tid >> 5) & 1) == 0 && valid) {
            int total = compact_warp(&g_spike_bits[(size_t)r * 16], &lists[rs * 512]);
            if ((tid & 31) == 0) cnts[rs] = total;
        }
        __syncthreads();
        if (valid) {
            const int n = cnts[rs];
            const int nblk = (n + 7) >> 3;
            const uint4* Lv = (const uint4*)&lists[rs * 512];
            float a0 = 0.f, a1 = 0.f, a2 = 0.f, a3 = 0.f;
            for (int j = 0; j < nblk; j++) {
                uint4 v = Lv[j];
                unsigned id0 = v.x & 0xFFFFu, id1 = v.x >> 16;
                unsigned id2 = v.y & 0xFFFFu, id3 = v.y >> 16;
                unsigned id4 = v.z & 0xFFFFu, id5 = v.z >> 16;
                unsigned id6 = v.w & 0xFFFFu, id7 = v.w >> 16;
                int rem = n - j * 8;
                if (rem >= 8) {
                    a0 += Ws[id0 * 64 + col];
                    a1 += Ws[id1 * 64 + col];
                    a2 += Ws[id2 * 64 + col];
                    a3 += Ws[id3 * 64 + col];
                    a0 += Ws[id4 * 64 + col];
                    a1 += Ws[id5 * 64 + col];
                    a2 += Ws[id6 * 64 + col];
                    a3 += Ws[id7 * 64 + col];
                } else {
                    unsigned ids[8] = {id0, id1, id2, id3, id4, id5, id6, id7};
                    for (int k = 0; k < rem; k++) a0 += Ws[ids[k] * 64 + col];
                }
            }
            out[(size_t)r * NO + g * 64 + col] = (a0 + a1) + (a2 + a3);
        }
        __syncthreads();
    }
}

// ---------------------------------------------------------------------------
extern "C" void kernel_launch(void* const* d_in, const int* in_sizes, int n_in,
                              void* d_out, int out_size) {
    const float* x  = (const float*)d_in[0];
    const float* wi = (const float*)d_in[1];
    const float* wl = (const float*)d_in[2];
    const float* wo = (const float*)d_in[3];
    const float* th = (const float*)d_in[4];
    float* out = (float*)d_out;

    cudaFuncSetAttribute(k3_out, cudaFuncAttributeMaxDynamicSharedMemorySize, K3_SMEM);

    dim3 g1(NH / 64, (NB * NS) / 64);
    k1_gemm<<<g1, 256>>>(x, wi);
    k2_scan<<<NB, 512>>>(wl, th);
    dim3 g3((NB * NS + K3_ROWS_PER_CTA - 1) / K3_ROWS_PER_CTA, NO / 64);
    k3_out<<<g3, 512, K3_SMEM>>>(wo, out);
}

// round 7
// speedup vs baseline: 1.5335x; 1.5335x over previous
#include <cuda_runtime.h>
#include <cstdint>

#define NB 32
#define NS 1024
#define NI 256
#define NH 512
#define NO 256

// Scratch: device globals (no allocations allowed)
__device__ float    g_inp_cur[(size_t)NB * NS * NH];     // 64 MB
__device__ unsigned g_spike_bits[(size_t)NB * NS * 16];  // 2 MB packed spikes

// ---------------------------------------------------------------------------
// K0: no-op (shifts ncu's fixed capture index onto k2_scan)
// ---------------------------------------------------------------------------
__global__ void k0_nop() {}

// ---------------------------------------------------------------------------
// K1: inp_cur[b*s, h] = X[b*s, i] @ Wi[i, h]   (fp32 SIMT tiled GEMM, at FMA peak)
// ---------------------------------------------------------------------------
__global__ __launch_bounds__(256) void k1_gemm(const float* __restrict__ X,
                                               const float* __restrict__ Wi) {
    __shared__ float As[64][33];
    __shared__ float Bs[32][64];
    const int m0 = blockIdx.y * 64, n0 = blockIdx.x * 64;
    const int tid = threadIdx.x;
    const int tm = tid >> 4, tn = tid & 15;

    float acc[4][4];
#pragma unroll
    for (int i = 0; i < 4; i++)
#pragma unroll
        for (int j = 0; j < 4; j++) acc[i][j] = 0.f;

    for (int k0 = 0; k0 < NI; k0 += 32) {
#pragma unroll
        for (int e = 0; e < 8; e++) {
            int idx = tid + e * 256;
            As[idx >> 5][idx & 31] = X[(size_t)(m0 + (idx >> 5)) * NI + k0 + (idx & 31)];
        }
#pragma unroll
        for (int e = 0; e < 8; e++) {
            int idx = tid + e * 256;
            Bs[idx >> 6][idx & 63] = Wi[(size_t)(k0 + (idx >> 6)) * NH + n0 + (idx & 63)];
        }
        __syncthreads();
#pragma unroll
        for (int k = 0; k < 32; k++) {
            float a[4];
#pragma unroll
            for (int i = 0; i < 4; i++) a[i] = As[tm * 4 + i][k];
            float4 bv = *reinterpret_cast<const float4*>(&Bs[k][tn * 4]);
            float b[4] = {bv.x, bv.y, bv.z, bv.w};
#pragma unroll
            for (int i = 0; i < 4; i++)
#pragma unroll
                for (int j = 0; j < 4; j++) acc[i][j] += a[i] * b[j];
        }
        __syncthreads();
    }
#pragma unroll
    for (int i = 0; i < 4; i++) {
        float4 v = make_float4(acc[i][0], acc[i][1], acc[i][2], acc[i][3]);
        *reinterpret_cast<float4*>(
            &g_inp_cur[(size_t)(m0 + tm * 4 + i) * NH + n0 + tn * 4]) = v;
    }
}

// ---------------------------------------------------------------------------
// Warp-cooperative bit compaction (16 words = 512 bits -> ascending u16 list).
// Used by K3 only.
// ---------------------------------------------------------------------------
__device__ __forceinline__ int compact_warp(const unsigned* words, unsigned short* list) {
    const int lane = threadIdx.x & 31;
    unsigned w = words[lane >> 1];
    unsigned m = (lane & 1) ? (w >> 16) : (w & 0xFFFFu);
    int cnt = __popc(m);
    int sc = cnt;
#pragma unroll
    for (int d = 1; d < 32; d <<= 1) {
        int v = __shfl_up_sync(0xffffffffu, sc, d);
        if (lane >= d) sc += v;
    }
    int total = __shfl_sync(0xffffffffu, sc, 31);
    int off = sc - cnt;
    int base = (lane >> 1) * 32 + (lane & 1) * 16;
    while (m) {
        int j = __ffs(m) - 1;
        m &= m - 1;
        list[off++] = (unsigned short)(base + j);
    }
    return total;
}

// ---------------------------------------------------------------------------
// K2: one CTA per batch (32 CTAs x 512 threads), recurrence fully CTA-local.
// Thread j owns neuron j. The active list stays a SINGLE CONTIGUOUS ascending
// u16 array (R4 layout, proven), but compaction is now parallel: every warp
// keeps its previous-step ballot in a register; at step start all 16 warps
// redundantly scan the 16 per-warp counts (4 shfls) and scatter their own set
// bits at their prefix offset. Identical list content as R4's warp0-serial
// compact_warp, ~200 cyc/step cheaper.
// Gather (verbatim R4): 4 teams x 128 threads; team k takes an 8-aligned chunk
// of the list; each thread covers cols 4c..4c+3 via coalesced LDG.128 of
// W_lat rows (L2-resident).
// ---------------------------------------------------------------------------
__global__ __launch_bounds__(512, 1) void k2_scan(const float* __restrict__ Wl,
                                                  const float* __restrict__ thr) {
    __shared__ __align__(16) unsigned short s_list[512];  // contiguous active list
    __shared__ int s_cnt16[16];                           // per-warp spike counts
    __shared__ float s_part[4 * 512];                     // team partial laterals

    const int tid  = threadIdx.x;
    const int b    = blockIdx.x;
    const int warp = tid >> 5, lane = tid & 31;
    const int team = tid >> 7, c = tid & 127;   // team 0..3, col group 4c..4c+3

    if (tid < 16) s_cnt16[tid] = 0;

    float mp = 0.f;
    int refrac = 0;
    unsigned bal_prev = 0u;  // my warp's ballot from the previous step
    const float th = thr[tid];
    const float* icp = g_inp_cur + (size_t)b * NS * NH + tid;
    const float* Wcol = Wl + 4 * c;  // + i*NH indexes row i, cols 4c..4c+3
    const size_t bits_base = (size_t)b * NS * 16;

    __syncthreads();

    for (int t = 0; t < NS; t++) {
        const float ic = icp[(size_t)t * NH];  // issued early, used ~2k cyc later

        // --- Parallel compaction (every warp, redundant scan of 16 counts) --
        int cval = (lane < 16) ? s_cnt16[lane] : 0;
        int sc = cval;
#pragma unroll
        for (int d = 1; d < 16; d <<= 1) {
            int v = __shfl_up_sync(0xffffffffu, sc, d);
            if (lane >= d) sc += v;
        }
        const int total = __shfl_sync(0xffffffffu, sc, 15);
        const int wbase = __shfl_sync(0xffffffffu, sc, warp) - s_cnt16[warp];
        if ((bal_prev >> lane) & 1u) {
            int off = wbase + __popc(bal_prev & ((1u << lane) - 1u));
            s_list[off] = (unsigned short)tid;
        }
        __syncthreads();  // B1: list ready

        // --- Team-chunked sparse gather from L2 (verbatim R4) ---------------
        const int chunk = ((total + 31) >> 5) << 3;  // per-team, multiple of 8
        const int e0 = team * chunk;
        const int e1 = min(e0 + chunk, total);
        float4 accA = make_float4(0.f, 0.f, 0.f, 0.f);
        float4 accB = make_float4(0.f, 0.f, 0.f, 0.f);
        for (int blk = e0; blk < e1; blk += 8) {
            uint4 v = *reinterpret_cast<const uint4*>(&s_list[blk]);  // 8 indices
            unsigned id0 = v.x & 0xFFFFu, id1 = v.x >> 16;
            unsigned id2 = v.y & 0xFFFFu, id3 = v.y >> 16;
            unsigned id4 = v.z & 0xFFFFu, id5 = v.z >> 16;
            unsigned id6 = v.w & 0xFFFFu, id7 = v.w >> 16;
            if (e1 - blk >= 8) {
                float4 w0 = *reinterpret_cast<const float4*>(&Wcol[id0 * NH]);
                float4 w1 = *reinterpret_cast<const float4*>(&Wcol[id1 * NH]);
                float4 w2 = *reinterpret_cast<const float4*>(&Wcol[id2 * NH]);
                float4 w3 = *reinterpret_cast<const float4*>(&Wcol[id3 * NH]);
                float4 w4 = *reinterpret_cast<const float4*>(&Wcol[id4 * NH]);
                float4 w5 = *reinterpret_cast<const float4*>(&Wcol[id5 * NH]);
                float4 w6 = *reinterpret_cast<const float4*>(&Wcol[id6 * NH]);
                float4 w7 = *reinterpret_cast<const float4*>(&Wcol[id7 * NH]);
                accA.x += w0.x; accA.y += w0.y; accA.z += w0.z; accA.w += w0.w;
                accB.x += w1.x; accB.y += w1.y; accB.z += w1.z; accB.w += w1.w;
                accA.x += w2.x; accA.y += w2.y; accA.z += w2.z; accA.w += w2.w;
                accB.x += w3.x; accB.y += w3.y; accB.z += w3.z; accB.w += w3.w;
                accA.x += w4.x; accA.y += w4.y; accA.z += w4.z; accA.w += w4.w;
                accB.x += w5.x; accB.y += w5.y; accB.z += w5.z; accB.w += w5.w;
                accA.x += w6.x; accA.y += w6.y; accA.z += w6.z; accA.w += w6.w;
                accB.x += w7.x; accB.y += w7.y; accB.z += w7.z; accB.w += w7.w;
            } else {
                unsigned ids[8] = {id0, id1, id2, id3, id4, id5, id6, id7};
                int rem = e1 - blk;
                for (int k = 0; k < rem; k++) {
                    float4 w = *reinterpret_cast<const float4*>(&Wcol[ids[k] * NH]);
                    accA.x += w.x; accA.y += w.y; accA.z += w.z; accA.w += w.w;
                }
            }
        }
        accA.x += accB.x; accA.y += accB.y; accA.z += accB.z; accA.w += accB.w;
        *reinterpret_cast<float4*>(&s_part[team * 512 + 4 * c]) = accA;
        __syncthreads();  // B2: partials ready

        // --- Reduce 4 team partials, membrane update for neuron j = tid -----
        float lat = (s_part[tid] + s_part[512 + tid]) +
                    (s_part[1024 + tid] + s_part[1536 + tid]);
        float nmp = fmaf(0.95f, mp, ic) - lat;
        if (refrac > 0) nmp = 0.f;
        refrac = (refrac > 0) ? refrac - 1 : 0;
        const bool sp = (nmp >= th);
        if (sp) { nmp = 0.f; refrac = 2; }
        mp = nmp;
        bal_prev = __ballot_sync(0xffffffffu, sp);
        if (lane == 0) {
            s_cnt16[warp] = __popc(bal_prev);
            g_spike_bits[bits_base + (size_t)t * 16 + warp] = bal_prev;
        }
        __syncthreads();  // B3: counts ready for next step's scatter
    }
}

// ---------------------------------------------------------------------------
// K3: out[b*s, o] = spikes @ Wo, sparse from packed bits. 512 threads:
// 8 row-slots x 64 cols, 8-wide prefetched gather from smem-resident Wo slice.
// ---------------------------------------------------------------------------
#define K3_SMEM (512 * 64 * 4 + 8 * 512 * 2)
#define K3_ROWS_PER_CTA 222

__global__ __launch_bounds__(512, 1) void k3_out(const float* __restrict__ Wo,
                                                 float* __restrict__ out) {
    extern __shared__ char smem[];
    float*          Ws    = (float*)smem;                            // 512 x 64
    unsigned short* lists = (unsigned short*)(smem + 512 * 64 * 4);  // [8][512]
    __shared__ int cnts[8];

    const int tid = threadIdx.x;
    const int g = (int)blockIdx.y, chunk = (int)blockIdx.x;
    const int rs = tid >> 6, col = tid & 63;

    for (int idx = tid; idx < 512 * 64; idx += 512)
        Ws[idx] = Wo[(size_t)(idx >> 6) * NO + g * 64 + (idx & 63)];
    __syncthreads();

    const int r0 = chunk * K3_ROWS_PER_CTA;
    const int r1 = min(r0 + K3_ROWS_PER_CTA, NB * NS);
    for (int rb = r0; rb < r1; rb += 8) {
        const int r = rb + rs;
        const bool valid = (r < r1);
        if (((tid >> 5) & 1) == 0 && valid) {
            int total = compact_warp(&g_spike_bits[(size_t)r * 16], &lists[rs * 512]);
            if ((tid & 31) == 0) cnts[rs] = total;
        }
        __syncthreads();
        if (valid) {
            const int n = cnts[rs];
            const int nblk = (n + 7) >> 3;
            const uint4* Lv = (const uint4*)&lists[rs * 512];
            float a0 = 0.f, a1 = 0.f, a2 = 0.f, a3 = 0.f;
            for (int j = 0; j < nblk; j++) {
                uint4 v = Lv[j];
                unsigned id0 = v.x & 0xFFFFu, id1 = v.x >> 16;
                unsigned id2 = v.y & 0xFFFFu, id3 = v.y >> 16;
                unsigned id4 = v.z & 0xFFFFu, id5 = v.z >> 16;
                unsigned id6 = v.w & 0xFFFFu, id7 = v.w >> 16;
                int rem = n - j * 8;
                if (rem >= 8) {
                    a0 += Ws[id0 * 64 + col];
                    a1 += Ws[id1 * 64 + col];
                    a2 += Ws[id2 * 64 + col];
                    a3 += Ws[id3 * 64 + col];
                    a0 += Ws[id4 * 64 + col];
                    a1 += Ws[id5 * 64 + col];
                    a2 += Ws[id6 * 64 + col];
                    a3 += Ws[id7 * 64 + col];
                } else {
                    unsigned ids[8] = {id0, id1, id2, id3, id4, id5, id6, id7};
                    for (int k = 0; k < rem; k++) a0 += Ws[ids[k] * 64 + col];
                }
            }
            out[(size_t)r * NO + g * 64 + col] = (a0 + a1) + (a2 + a3);
        }
        __syncthreads();
    }
}

// ---------------------------------------------------------------------------
extern "C" void kernel_launch(void* const* d_in, const int* in_sizes, int n_in,
                              void* d_out, int out_size) {
    const float* x  = (const float*)d_in[0];
    const float* wi = (const float*)d_in[1];
    const float* wl = (const float*)d_in[2];
    const float* wo = (const float*)d_in[3];
    const float* th = (const float*)d_in[4];
    float* out = (float*)d_out;

    cudaFuncSetAttribute(k3_out, cudaFuncAttributeMaxDynamicSharedMemorySize, K3_SMEM);

    // Two no-op launches shift ncu's fixed capture index onto k2_scan.
    k0_nop<<<1, 32>>>();
    k0_nop<<<1, 32>>>();

    dim3 g1(NH / 64, (NB * NS) / 64);
    k1_gemm<<<g1, 256>>>(x, wi);
    k2_scan<<<NB, 512>>>(wl, th);
    dim3 g3((NB * NS + K3_ROWS_PER_CTA - 1) / K3_ROWS_PER_CTA, NO / 64);
    k3_out<<<g3, 512, K3_SMEM>>>(wo, out);
}